// round 1
// baseline (speedup 1.0000x reference)
#include <cuda_runtime.h>
#include <cuda_bf16.h>
#include <math.h>

// Problem constants
constexpr int B   = 8;
constexpr int R   = 128;
constexpr int H   = 256;
constexpr int IND = 512;
constexpr int L   = 3;
constexpr int NH  = 4;
constexpr int DH  = 64;

constexpr int SZ = B * R * H;  // 262144

// Scratch layout inside one big device buffer
constexpr int OFF_H    = 0;
constexpr int OFF_AACT = SZ;
constexpr int OFF_BB   = 2 * SZ;
constexpr int OFF_AGG  = 3 * SZ;
constexpr int OFF_UPRE = 4 * SZ;
constexpr int OFF_U    = 5 * SZ;
constexpr int OFF_Q    = 6 * SZ;
constexpr int OFF_K    = 7 * SZ;
constexpr int OFF_V    = 8 * SZ;
constexpr int OFF_AO   = 9 * SZ;
constexpr int OFF_ADJ  = 10 * SZ;                 // R*R
constexpr int OFF_RS   = OFF_ADJ + R * R;         // R
constexpr int OFF_W2U  = OFF_RS + R;              // L*H*H
constexpr int OFF_C2   = OFF_W2U + L * H * H;     // L*H
constexpr int OFF_ABAR = OFF_C2 + L * H;          // B*H
constexpr int TOTAL    = OFF_ABAR + B * H;

__device__ float g_buf[TOTAL];

// ---------------------------------------------------------------------------
// A = sigmoid(rule_adj) * (1 - I); rowsum[i] = sum_j A[i,j]
__global__ void prep_A_kernel(const float* __restrict__ rule_adj,
                              float* __restrict__ A, float* __restrict__ rowsum) {
    int i = blockIdx.x, j = threadIdx.x;
    float v = rule_adj[i * R + j];
    float s = 1.f / (1.f + expf(-v));
    if (i == j) s = 0.f;
    A[i * R + j] = s;
    __shared__ float red[4];
    float t = s;
    for (int o = 16; o; o >>= 1) t += __shfl_xor_sync(0xffffffffu, t, o);
    if ((j & 31) == 0) red[j >> 5] = t;
    __syncthreads();
    if (j == 0) rowsum[i] = red[0] + red[1] + red[2] + red[3];
}

// ---------------------------------------------------------------------------
// h0 = x @ We + be, broadcast over R into h[B,R,H]
__global__ void h0_kernel(const float* __restrict__ x, const float* __restrict__ We,
                          const float* __restrict__ be, float* __restrict__ h) {
    __shared__ float xs[IND];
    int b = blockIdx.x, t = threadIdx.x;
    xs[t]       = x[b * IND + t];
    xs[t + 256] = x[b * IND + 256 + t];
    __syncthreads();
    float acc = be[t];
    #pragma unroll 8
    for (int k = 0; k < IND; k++) acc += xs[k] * We[k * H + t];
    for (int r = 0; r < R; r++) h[(b * R + r) * H + t] = acc;
}

// ---------------------------------------------------------------------------
// c2[l] = msg_b2[l] @ upd_W1b[l]
__global__ void c2_kernel(const float* __restrict__ msg_b2,
                          const float* __restrict__ upd_W1, float* __restrict__ c2) {
    __shared__ float bs[H];
    int l = blockIdx.x, t = threadIdx.x;
    bs[t] = msg_b2[l * H + t];
    __syncthreads();
    const float* W = upd_W1 + l * 2 * H * H + H * H;
    float acc = 0.f;
    #pragma unroll 8
    for (int k = 0; k < H; k++) acc += bs[k] * W[k * H + t];
    c2[l * H + t] = acc;
}

// ---------------------------------------------------------------------------
// Generic tiled GEMM: C = act(A1@W1 [+ A2@W2] [+ bias[n]] [+ rowv[m&127]*colv[n]])
// BM=32, BN=64, BK=32, 256 threads, each thread 2x4 outputs.
// Dims must be multiples of the tiles (true for all uses here).
__global__ __launch_bounds__(256) void gemm_kernel(
    const float* __restrict__ A1, const float* __restrict__ W1,
    const float* __restrict__ A2, const float* __restrict__ W2,
    const float* __restrict__ bias, const float* __restrict__ rowv,
    const float* __restrict__ colv, float* __restrict__ C,
    int M, int N, int K, int do_relu)
{
    __shared__ float As[32][33];
    __shared__ float Ws[32][64];
    const int m0 = blockIdx.y * 32, n0 = blockIdx.x * 64;
    const int tx = threadIdx.x & 15, ty = threadIdx.x >> 4;
    float acc[2][4];
    #pragma unroll
    for (int i = 0; i < 2; i++)
        #pragma unroll
        for (int j = 0; j < 4; j++) acc[i][j] = 0.f;

    const int npass = (A2 != nullptr) ? 2 : 1;
    for (int pass = 0; pass < npass; pass++) {
        const float* Ap = pass ? A2 : A1;
        const float* Wp = pass ? W2 : W1;
        for (int k0 = 0; k0 < K; k0 += 32) {
            #pragma unroll
            for (int idx = threadIdx.x; idx < 1024; idx += 256) {
                int c = idx & 31, r = idx >> 5;
                As[c][r] = Ap[(m0 + r) * K + k0 + c];
            }
            #pragma unroll
            for (int idx = threadIdx.x; idx < 2048; idx += 256) {
                int n = idx & 63, c = idx >> 6;
                Ws[c][n] = Wp[(k0 + c) * N + n0 + n];
            }
            __syncthreads();
            #pragma unroll
            for (int kk = 0; kk < 32; kk++) {
                float a0 = As[kk][ty * 2 + 0];
                float a1 = As[kk][ty * 2 + 1];
                float4 bv = *(const float4*)&Ws[kk][tx * 4];
                acc[0][0] += a0 * bv.x; acc[0][1] += a0 * bv.y;
                acc[0][2] += a0 * bv.z; acc[0][3] += a0 * bv.w;
                acc[1][0] += a1 * bv.x; acc[1][1] += a1 * bv.y;
                acc[1][2] += a1 * bv.z; acc[1][3] += a1 * bv.w;
            }
            __syncthreads();
        }
    }
    #pragma unroll
    for (int i = 0; i < 2; i++) {
        int m = m0 + ty * 2 + i;
        float rb = rowv ? rowv[m & (R - 1)] : 0.f;
        #pragma unroll
        for (int j = 0; j < 4; j++) {
            int n = n0 + tx * 4 + j;
            float v = acc[i][j];
            if (bias) v += bias[n];
            if (rowv) v += rb * colv[n];
            if (do_relu) v = fmaxf(v, 0.f);
            C[m * N + n] = v;
        }
    }
}

// ---------------------------------------------------------------------------
// aggpre[b,i,h] = sum_j A[i,j] * relu(a[b,i,h] + bb[b,j,h] + b1[h])
// grid (hchunk=4, ichunk=4, b=8), 256 threads. bb tile (+b1 folded) in smem.
__global__ __launch_bounds__(256) void agg_kernel(
    const float* __restrict__ a, const float* __restrict__ bbg,
    const float* __restrict__ b1, const float* __restrict__ A,
    float* __restrict__ out)
{
    __shared__ float bbs[128 * 64];
    int hc = blockIdx.x * 64, ic = blockIdx.y * 32, b = blockIdx.z;
    int t = threadIdx.x;
    const float* bp = bbg + b * R * H;
    for (int idx = t; idx < 128 * 64; idx += 256) {
        int j = idx >> 6, c = idx & 63;
        bbs[j * 64 + c] = bp[j * H + hc + c] + b1[hc + c];
    }
    __syncthreads();
    int hl = (t & 15) * 4;
    int i0 = ic + (t >> 4) * 2;
    float4 av0 = *(const float4*)&a[(b * R + i0) * H + hc + hl];
    float4 av1 = *(const float4*)&a[(b * R + i0 + 1) * H + hc + hl];
    float4 ac0 = {0, 0, 0, 0}, ac1 = {0, 0, 0, 0};
    const float* Ar = A + i0 * R;
    #pragma unroll 4
    for (int j = 0; j < R; j++) {
        float4 bv = *(const float4*)&bbs[j * 64 + hl];
        float w0 = __ldg(&Ar[j]);
        float w1 = __ldg(&Ar[R + j]);
        ac0.x += w0 * fmaxf(av0.x + bv.x, 0.f);
        ac0.y += w0 * fmaxf(av0.y + bv.y, 0.f);
        ac0.z += w0 * fmaxf(av0.z + bv.z, 0.f);
        ac0.w += w0 * fmaxf(av0.w + bv.w, 0.f);
        ac1.x += w1 * fmaxf(av1.x + bv.x, 0.f);
        ac1.y += w1 * fmaxf(av1.y + bv.y, 0.f);
        ac1.z += w1 * fmaxf(av1.z + bv.z, 0.f);
        ac1.w += w1 * fmaxf(av1.w + bv.w, 0.f);
    }
    *(float4*)&out[(b * R + i0) * H + hc + hl]     = ac0;
    *(float4*)&out[(b * R + i0 + 1) * H + hc + hl] = ac1;
}

// ---------------------------------------------------------------------------
// h = LayerNorm(h + u) * g + beta   (u already contains upd_b2)
__global__ void ln_kernel(float* __restrict__ h, const float* __restrict__ u,
                          const float* __restrict__ gg, const float* __restrict__ bb) {
    __shared__ float red[8];
    int row = blockIdx.x, t = threadIdx.x;
    int o = row * H + t;
    float x = h[o] + u[o];
    float s = x;
    for (int k = 16; k; k >>= 1) s += __shfl_xor_sync(0xffffffffu, s, k);
    if ((t & 31) == 0) red[t >> 5] = s;
    __syncthreads();
    if (t < 32) {
        float v = (t < 8) ? red[t] : 0.f;
        for (int k = 4; k; k >>= 1) v += __shfl_xor_sync(0xffffffffu, v, k);
        if (t == 0) red[0] = v;
    }
    __syncthreads();
    float mu = red[0] * (1.f / H);
    __syncthreads();
    float d = x - mu;
    float q = d * d;
    for (int k = 16; k; k >>= 1) q += __shfl_xor_sync(0xffffffffu, q, k);
    if ((t & 31) == 0) red[t >> 5] = q;
    __syncthreads();
    if (t < 32) {
        float v = (t < 8) ? red[t] : 0.f;
        for (int k = 4; k; k >>= 1) v += __shfl_xor_sync(0xffffffffu, v, k);
        if (t == 0) red[0] = v;
    }
    __syncthreads();
    float var = red[0] * (1.f / H);
    h[o] = d * rsqrtf(var + 1e-5f) * gg[t] + bb[t];
}

// ---------------------------------------------------------------------------
// Multi-head attention for one (b, head, q-chunk of 16 rows). Everything in smem.
__global__ __launch_bounds__(256) void attn_kernel(
    const float* __restrict__ q, const float* __restrict__ k,
    const float* __restrict__ v, float* __restrict__ ao)
{
    __shared__ float ks[128 * 65];   // k tile, pitch 65 (also reused for v, pitch 64)
    __shared__ float qs[16 * 64];
    __shared__ float ls[16 * 128];
    int qc = blockIdx.x, head = blockIdx.y, b = blockIdx.z;
    int t = threadIdx.x;

    const float* kb = k + b * R * H + head * DH;
    for (int idx = t; idx < 128 * 64; idx += 256) {
        int j = idx >> 6, d = idx & 63;
        ks[j * 65 + d] = kb[j * H + d];
    }
    const float* qb = q + (b * R + qc * 16) * H + head * DH;
    for (int idx = t; idx < 16 * 64; idx += 256) {
        int r = idx >> 6, d = idx & 63;
        qs[r * 64 + d] = qb[r * H + d];
    }
    __syncthreads();

    {   // logits: thread (g, j) computes 8 q-rows against column j
        int j = t & 127, g = t >> 7;
        float acc[8];
        #pragma unroll
        for (int r = 0; r < 8; r++) acc[r] = 0.f;
        for (int d = 0; d < 64; d++) {
            float kv = ks[j * 65 + d];
            #pragma unroll
            for (int r = 0; r < 8; r++) acc[r] += qs[(g * 8 + r) * 64 + d] * kv;
        }
        #pragma unroll
        for (int r = 0; r < 8; r++) ls[(g * 8 + r) * 128 + j] = acc[r] * 0.125f;
    }
    __syncthreads();

    {   // row softmax: 16 lanes per row, 8 cols each
        int qr = t >> 4, jc = t & 15;
        float e[8]; float mx = -3e38f;
        #pragma unroll
        for (int jj = 0; jj < 8; jj++) {
            e[jj] = ls[qr * 128 + jc * 8 + jj];
            mx = fmaxf(mx, e[jj]);
        }
        for (int o = 8; o; o >>= 1) mx = fmaxf(mx, __shfl_xor_sync(0xffffffffu, mx, o));
        float s = 0.f;
        #pragma unroll
        for (int jj = 0; jj < 8; jj++) { e[jj] = expf(e[jj] - mx); s += e[jj]; }
        for (int o = 8; o; o >>= 1) s += __shfl_xor_sync(0xffffffffu, s, o);
        float inv = 1.f / s;
        #pragma unroll
        for (int jj = 0; jj < 8; jj++) ls[qr * 128 + jc * 8 + jj] = e[jj] * inv;
    }
    // load v into the (now free) k-tile region, pitch 64
    float* vs = ks;
    const float* vb = v + b * R * H + head * DH;
    for (int idx = t; idx < 128 * 64; idx += 256) {
        int j = idx >> 6, d = idx & 63;
        vs[j * 64 + d] = vb[j * H + d];
    }
    __syncthreads();

    {   // out = P @ V
        int qr = t >> 4, d4 = (t & 15) * 4;
        float4 acc = {0, 0, 0, 0};
        for (int j = 0; j < 128; j++) {
            float p = ls[qr * 128 + j];
            float4 vv = *(const float4*)&vs[j * 64 + d4];
            acc.x += p * vv.x; acc.y += p * vv.y;
            acc.z += p * vv.z; acc.w += p * vv.w;
        }
        *(float4*)&ao[(b * R + qc * 16 + qr) * H + head * DH + d4] = acc;
    }
}

// ---------------------------------------------------------------------------
// abar[b,:] = mean_r ao[b,r,:]
__global__ void mean_kernel(const float* __restrict__ ao, float* __restrict__ abar) {
    int b = blockIdx.x, t = threadIdx.x;
    float s = 0.f;
    for (int r = 0; r < R; r++) s += ao[(b * R + r) * H + t];
    abar[b * H + t] = s * (1.f / R);
}

// ---------------------------------------------------------------------------
// g = abar@Wo + bo; t = relu(g@roW1+rob1); logits = t@roW2+rob2; softmax -> out
__global__ void readout_kernel(const float* __restrict__ abar,
                               const float* __restrict__ Wo, const float* __restrict__ bo,
                               const float* __restrict__ roW1, const float* __restrict__ rob1,
                               const float* __restrict__ roW2, const float* __restrict__ rob2,
                               float* __restrict__ out) {
    __shared__ float s0[H], s1[H];
    __shared__ float red[8];
    int b = blockIdx.x, t = threadIdx.x;
    s0[t] = abar[b * H + t];
    __syncthreads();
    float acc = bo[t];
    #pragma unroll 8
    for (int k = 0; k < H; k++) acc += s0[k] * Wo[k * H + t];
    s1[t] = acc;
    __syncthreads();
    acc = rob1[t];
    #pragma unroll 8
    for (int k = 0; k < H; k++) acc += s1[k] * roW1[k * H + t];
    __syncthreads();
    s0[t] = fmaxf(acc, 0.f);
    __syncthreads();
    float lg = -3e38f;
    if (t < R) {
        lg = rob2[t];
        #pragma unroll 8
        for (int k = 0; k < H; k++) lg += s0[k] * roW2[k * R + t];
    }
    float m = lg;
    for (int k = 16; k; k >>= 1) m = fmaxf(m, __shfl_xor_sync(0xffffffffu, m, k));
    if ((t & 31) == 0) red[t >> 5] = m;
    __syncthreads();
    if (t < 32) {
        float v = (t < 8) ? red[t] : -3e38f;
        for (int k = 4; k; k >>= 1) v = fmaxf(v, __shfl_xor_sync(0xffffffffu, v, k));
        if (t == 0) red[0] = v;
    }
    __syncthreads();
    float mx = red[0];
    __syncthreads();
    float e = (t < R) ? expf(lg - mx) : 0.f;
    float s = e;
    for (int k = 16; k; k >>= 1) s += __shfl_xor_sync(0xffffffffu, s, k);
    if ((t & 31) == 0) red[t >> 5] = s;
    __syncthreads();
    if (t < 32) {
        float v = (t < 8) ? red[t] : 0.f;
        for (int k = 4; k; k >>= 1) v += __shfl_xor_sync(0xffffffffu, v, k);
        if (t == 0) red[0] = v;
    }
    __syncthreads();
    float sum = red[0];
    if (t < R) out[b * R + t] = e / sum;
}

// ---------------------------------------------------------------------------
extern "C" void kernel_launch(void* const* d_in, const int* in_sizes, int n_in,
                              void* d_out, int out_size) {
    const float* x       = (const float*)d_in[0];
    const float* We      = (const float*)d_in[1];
    const float* be      = (const float*)d_in[2];
    const float* msg_W1  = (const float*)d_in[3];
    const float* msg_b1  = (const float*)d_in[4];
    const float* msg_W2  = (const float*)d_in[5];
    const float* msg_b2  = (const float*)d_in[6];
    const float* upd_W1  = (const float*)d_in[7];
    const float* upd_b1  = (const float*)d_in[8];
    const float* upd_W2  = (const float*)d_in[9];
    const float* upd_b2  = (const float*)d_in[10];
    const float* ln_g    = (const float*)d_in[11];
    const float* ln_b    = (const float*)d_in[12];
    const float* rule_adj= (const float*)d_in[13];
    const float* Wq      = (const float*)d_in[14];
    const float* bq      = (const float*)d_in[15];
    const float* Wk      = (const float*)d_in[16];
    const float* bk      = (const float*)d_in[17];
    const float* Wv      = (const float*)d_in[18];
    const float* bv      = (const float*)d_in[19];
    const float* Wo      = (const float*)d_in[20];
    const float* bo      = (const float*)d_in[21];
    const float* roW1    = (const float*)d_in[22];
    const float* rob1    = (const float*)d_in[23];
    const float* roW2    = (const float*)d_in[24];
    const float* rob2    = (const float*)d_in[25];
    float* out = (float*)d_out;

    float* base = nullptr;
    cudaGetSymbolAddress((void**)&base, g_buf);
    float* hb    = base + OFF_H;
    float* aact  = base + OFF_AACT;
    float* bbb   = base + OFF_BB;
    float* aggb  = base + OFF_AGG;
    float* upreb = base + OFF_UPRE;
    float* ub    = base + OFF_U;
    float* qb    = base + OFF_Q;
    float* kb    = base + OFF_K;
    float* vb    = base + OFF_V;
    float* aob   = base + OFF_AO;
    float* Ab    = base + OFF_ADJ;
    float* rsb   = base + OFF_RS;
    float* w2ub  = base + OFF_W2U;
    float* c2b   = base + OFF_C2;
    float* abarb = base + OFF_ABAR;

    const int M = B * R;  // 1024
    dim3 gBig(H / 64, M / 32);   // (4, 32)
    dim3 gSq(H / 64, H / 32);    // (4, 8)

    prep_A_kernel<<<R, R>>>(rule_adj, Ab, rsb);
    h0_kernel<<<B, H>>>(x, We, be, hb);
    c2_kernel<<<L, H>>>(msg_b2, upd_W1, c2b);
    for (int l = 0; l < L; l++) {
        gemm_kernel<<<gSq, 256>>>(msg_W2 + l * H * H, upd_W1 + l * 2 * H * H + H * H,
                                  nullptr, nullptr, nullptr, nullptr, nullptr,
                                  w2ub + l * H * H, H, H, H, 0);
    }

    for (int l = 0; l < L; l++) {
        const float* W1a = msg_W1 + l * 2 * H * H;
        const float* W1b = W1a + H * H;
        gemm_kernel<<<gBig, 256>>>(hb, W1a, nullptr, nullptr, nullptr, nullptr, nullptr,
                                   aact, M, H, H, 0);
        gemm_kernel<<<gBig, 256>>>(hb, W1b, nullptr, nullptr, nullptr, nullptr, nullptr,
                                   bbb, M, H, H, 0);
        agg_kernel<<<dim3(4, 4, B), 256>>>(aact, bbb, msg_b1 + l * H, Ab, aggb);
        // upre = relu(h@Wu1a + aggpre@W2u + rowsumA[i]*c2 + upd_b1)
        gemm_kernel<<<gBig, 256>>>(hb, upd_W1 + l * 2 * H * H,
                                   aggb, w2ub + l * H * H,
                                   upd_b1 + l * H, rsb, c2b + l * H,
                                   upreb, M, H, H, 1);
        // u = upre@Wu2 + upd_b2
        gemm_kernel<<<gBig, 256>>>(upreb, upd_W2 + l * H * H, nullptr, nullptr,
                                   upd_b2 + l * H, nullptr, nullptr,
                                   ub, M, H, H, 0);
        ln_kernel<<<M, H>>>(hb, ub, ln_g + l * H, ln_b + l * H);
    }

    gemm_kernel<<<gBig, 256>>>(hb, Wq, nullptr, nullptr, bq, nullptr, nullptr, qb, M, H, H, 0);
    gemm_kernel<<<gBig, 256>>>(hb, Wk, nullptr, nullptr, bk, nullptr, nullptr, kb, M, H, H, 0);
    gemm_kernel<<<gBig, 256>>>(hb, Wv, nullptr, nullptr, bv, nullptr, nullptr, vb, M, H, H, 0);
    attn_kernel<<<dim3(R / 16, NH, B), 256>>>(qb, kb, vb, aob);
    mean_kernel<<<B, H>>>(aob, abarb);
    readout_kernel<<<B, H>>>(abarb, Wo, bo, roW1, rob1, roW2, rob2, out);
    (void)in_sizes; (void)n_in; (void)out_size;
}

// round 3
// speedup vs baseline: 1.3119x; 1.3119x over previous
#include <cuda_runtime.h>
#include <cuda_bf16.h>
#include <math.h>

// Problem constants
constexpr int B   = 8;
constexpr int R   = 128;
constexpr int H   = 256;
constexpr int IND = 512;
constexpr int L   = 3;
constexpr int NH  = 4;
constexpr int DH  = 64;

constexpr int SZ = B * R * H;  // 262144
constexpr int HH = H * H;

// Scratch layout inside one big device buffer
constexpr int OFF_H    = 0;
constexpr int OFF_AACT = SZ;
constexpr int OFF_BB   = 2 * SZ;
constexpr int OFF_AGG  = 3 * SZ;
constexpr int OFF_HU   = 4 * SZ;
constexpr int OFF_UPRE = 5 * SZ;
constexpr int OFF_U    = 6 * SZ;
constexpr int OFF_Q    = 7 * SZ;
constexpr int OFF_K    = 8 * SZ;
constexpr int OFF_V    = 9 * SZ;
constexpr int OFF_AO   = 10 * SZ;
constexpr int OFF_ADJ  = 11 * SZ;                 // R*R
constexpr int OFF_RS   = OFF_ADJ + R * R;         // R
constexpr int OFF_W2U  = OFF_RS + R;              // L*H*H
constexpr int OFF_C2   = OFF_W2U + L * HH;        // L*H
constexpr int TOTAL    = OFF_C2 + L * H;

__device__ float g_buf[TOTAL];

typedef unsigned long long u64;

__device__ __forceinline__ u64 pack2(float x) {
    u64 r; asm("mov.b64 %0, {%1, %1};" : "=l"(r) : "f"(x)); return r;
}
__device__ __forceinline__ void fma2(u64& d, u64 a, u64 b) {
    asm("fma.rn.f32x2 %0, %1, %2, %0;" : "+l"(d) : "l"(a), "l"(b));
}
__device__ __forceinline__ float2 unpack2(u64 v) {
    float2 f; asm("mov.b64 {%0, %1}, %2;" : "=f"(f.x), "=f"(f.y) : "l"(v)); return f;
}

// ---------------------------------------------------------------------------
// A = sigmoid(rule_adj) * (1 - I); rowsum[i] = sum_j A[i,j]
__global__ void prep_A_kernel(const float* __restrict__ rule_adj,
                              float* __restrict__ A, float* __restrict__ rowsum) {
    int i = blockIdx.x, j = threadIdx.x;
    float v = rule_adj[i * R + j];
    float s = 1.f / (1.f + expf(-v));
    if (i == j) s = 0.f;
    A[i * R + j] = s;
    __shared__ float red[4];
    float t = s;
    for (int o = 16; o; o >>= 1) t += __shfl_xor_sync(0xffffffffu, t, o);
    if ((j & 31) == 0) red[j >> 5] = t;
    __syncthreads();
    if (j == 0) rowsum[i] = red[0] + red[1] + red[2] + red[3];
}

// ---------------------------------------------------------------------------
// h0 = x @ We + be, broadcast over R into h[B,R,H]
__global__ void h0_kernel(const float* __restrict__ x, const float* __restrict__ We,
                          const float* __restrict__ be, float* __restrict__ h) {
    __shared__ float xs[IND];
    int b = blockIdx.x, t = threadIdx.x;
    xs[t]       = x[b * IND + t];
    xs[t + 256] = x[b * IND + 256 + t];
    __syncthreads();
    float acc = be[t];
    #pragma unroll 8
    for (int k = 0; k < IND; k++) acc += xs[k] * We[k * H + t];
    for (int r = 0; r < R; r++) h[(b * R + r) * H + t] = acc;
}

// ---------------------------------------------------------------------------
// c2[l] = msg_b2[l] @ upd_W1b[l]
__global__ void c2_kernel(const float* __restrict__ msg_b2,
                          const float* __restrict__ upd_W1, float* __restrict__ c2) {
    __shared__ float bs[H];
    int l = blockIdx.x, t = threadIdx.x;
    bs[t] = msg_b2[l * H + t];
    __syncthreads();
    const float* W = upd_W1 + l * 2 * HH + HH;
    float acc = 0.f;
    #pragma unroll 8
    for (int k = 0; k < H; k++) acc += bs[k] * W[k * H + t];
    c2[l * H + t] = acc;
}

// ---------------------------------------------------------------------------
// GEMM: C = act(A@W [+ addend] [+ bias[n]] [+ rowv[m&127]*colv[n]])
// N = K = 256 fixed. BM=32, BN=64, BK=32, 256 threads, 2x4 outputs per thread.
// Double-buffered smem, packed fma.rn.f32x2 accumulation (bit-identical to FFMA).
// Up to 3 independent jobs selected by blockIdx.z.
struct GemmJob {
    const float* A;
    const float* W;
    const float* bias;    // [256] or null
    const float* rowv;    // [128] or null (indexed m & 127)
    const float* colv;    // [256] (with rowv)
    const float* addend;  // [M,256] or null
    float* C;
    int relu;
};

__global__ __launch_bounds__(256) void gemm_kernel(GemmJob j0, GemmJob j1, GemmJob j2, int M) {
    __shared__ float As[2][32 * 36];
    __shared__ float Ws[2][32 * 64];

    GemmJob job = (blockIdx.z == 0) ? j0 : ((blockIdx.z == 1) ? j1 : j2);
    const float* __restrict__ A = job.A;
    const float* __restrict__ W = job.W;

    const int m0 = blockIdx.y * 32, n0 = blockIdx.x * 64;
    const int tid = threadIdx.x;
    const int tx = tid & 15, ty = tid >> 4;

    // load mappings
    const int ar = tid >> 3, ac4 = (tid & 7) * 4;             // A: 1 float4/thread
    const int wc0 = tid >> 4, wn0 = (tid & 15) * 4;           // W: 2 float4/thread
    const int wc1 = (tid + 256) >> 4, wn1 = wn0;

    u64 acc[2][2];
    acc[0][0] = acc[0][1] = acc[1][0] = acc[1][1] = 0ull;

    // prologue: load tile 0
    float4 aR = *(const float4*)&A[(m0 + ar) * 256 + ac4];
    float4 wR0 = *(const float4*)&W[wc0 * 256 + n0 + wn0];
    float4 wR1 = *(const float4*)&W[wc1 * 256 + n0 + wn1];
    *(float4*)&As[0][ar * 36 + ac4] = aR;
    *(float4*)&Ws[0][wc0 * 64 + wn0] = wR0;
    *(float4*)&Ws[0][wc1 * 64 + wn1] = wR1;
    __syncthreads();

    #pragma unroll 1
    for (int t = 0; t < 8; t++) {
        const int cur = t & 1;
        const bool has_next = (t < 7);
        if (has_next) {
            const int k0 = (t + 1) * 32;
            aR  = *(const float4*)&A[(m0 + ar) * 256 + k0 + ac4];
            wR0 = *(const float4*)&W[(k0 + wc0) * 256 + n0 + wn0];
            wR1 = *(const float4*)&W[(k0 + wc1) * 256 + n0 + wn1];
        }
        const float* __restrict__ as = As[cur];
        const float* __restrict__ ws = Ws[cur];
        #pragma unroll
        for (int kk = 0; kk < 32; kk++) {
            ulonglong2 bv = *(const ulonglong2*)&ws[kk * 64 + tx * 4];
            u64 pa0 = pack2(as[(ty * 2 + 0) * 36 + kk]);
            u64 pa1 = pack2(as[(ty * 2 + 1) * 36 + kk]);
            fma2(acc[0][0], pa0, bv.x);
            fma2(acc[0][1], pa0, bv.y);
            fma2(acc[1][0], pa1, bv.x);
            fma2(acc[1][1], pa1, bv.y);
        }
        if (has_next) {
            const int nxt = cur ^ 1;
            *(float4*)&As[nxt][ar * 36 + ac4] = aR;
            *(float4*)&Ws[nxt][wc0 * 64 + wn0] = wR0;
            *(float4*)&Ws[nxt][wc1 * 64 + wn1] = wR1;
        }
        __syncthreads();
    }

    const int n = n0 + tx * 4;
    #pragma unroll
    for (int i = 0; i < 2; i++) {
        const int m = m0 + ty * 2 + i;
        float2 p0 = unpack2(acc[i][0]);
        float2 p1 = unpack2(acc[i][1]);
        float4 v = make_float4(p0.x, p0.y, p1.x, p1.y);
        if (job.addend) {
            float4 ad = *(const float4*)&job.addend[m * 256 + n];
            v.x += ad.x; v.y += ad.y; v.z += ad.z; v.w += ad.w;
        }
        if (job.bias) {
            float4 bi = *(const float4*)&job.bias[n];
            v.x += bi.x; v.y += bi.y; v.z += bi.z; v.w += bi.w;
        }
        if (job.rowv) {
            float rv = job.rowv[m & (R - 1)];
            float4 cv = *(const float4*)&job.colv[n];
            v.x += rv * cv.x; v.y += rv * cv.y; v.z += rv * cv.z; v.w += rv * cv.w;
        }
        if (job.relu) {
            v.x = fmaxf(v.x, 0.f); v.y = fmaxf(v.y, 0.f);
            v.z = fmaxf(v.z, 0.f); v.w = fmaxf(v.w, 0.f);
        }
        *(float4*)&job.C[m * 256 + n] = v;
    }
}

// ---------------------------------------------------------------------------
// aggpre[b,i,h] = sum_j A[i,j] * relu(a[b,i,h] + bb[b,j,h])   (b1 folded into bb)
// grid (hchunk=4, ichunk=4, b=8), 256 threads. bb tile in smem.
__global__ __launch_bounds__(256) void agg_kernel(
    const float* __restrict__ a, const float* __restrict__ bbg,
    const float* __restrict__ A, float* __restrict__ out)
{
    __shared__ float bbs[128 * 64];
    int hc = blockIdx.x * 64, ic = blockIdx.y * 32, b = blockIdx.z;
    int t = threadIdx.x;
    const float* bp = bbg + b * R * H;
    for (int idx = t; idx < 128 * 64; idx += 256) {
        int j = idx >> 6, c = idx & 63;
        bbs[j * 64 + c] = bp[j * H + hc + c];
    }
    __syncthreads();
    int hl = (t & 15) * 4;
    int i0 = ic + (t >> 4) * 2;
    float4 av0 = *(const float4*)&a[(b * R + i0) * H + hc + hl];
    float4 av1 = *(const float4*)&a[(b * R + i0 + 1) * H + hc + hl];
    float4 ac0 = {0, 0, 0, 0}, ac1 = {0, 0, 0, 0};
    const float* Ar = A + i0 * R;
    #pragma unroll 4
    for (int j = 0; j < R; j++) {
        float4 bv = *(const float4*)&bbs[j * 64 + hl];
        float w0 = __ldg(&Ar[j]);
        float w1 = __ldg(&Ar[R + j]);
        ac0.x += w0 * fmaxf(av0.x + bv.x, 0.f);
        ac0.y += w0 * fmaxf(av0.y + bv.y, 0.f);
        ac0.z += w0 * fmaxf(av0.z + bv.z, 0.f);
        ac0.w += w0 * fmaxf(av0.w + bv.w, 0.f);
        ac1.x += w1 * fmaxf(av1.x + bv.x, 0.f);
        ac1.y += w1 * fmaxf(av1.y + bv.y, 0.f);
        ac1.z += w1 * fmaxf(av1.z + bv.z, 0.f);
        ac1.w += w1 * fmaxf(av1.w + bv.w, 0.f);
    }
    *(float4*)&out[(b * R + i0) * H + hc + hl]     = ac0;
    *(float4*)&out[(b * R + i0 + 1) * H + hc + hl] = ac1;
}

// ---------------------------------------------------------------------------
// h = LayerNorm(h + u) * g + beta   (u already contains upd_b2)
__global__ void ln_kernel(float* __restrict__ h, const float* __restrict__ u,
                          const float* __restrict__ gg, const float* __restrict__ bb) {
    __shared__ float red[8];
    int row = blockIdx.x, t = threadIdx.x;
    int o = row * H + t;
    float x = h[o] + u[o];
    float s = x;
    for (int k = 16; k; k >>= 1) s += __shfl_xor_sync(0xffffffffu, s, k);
    if ((t & 31) == 0) red[t >> 5] = s;
    __syncthreads();
    if (t < 32) {
        float v = (t < 8) ? red[t] : 0.f;
        for (int k = 4; k; k >>= 1) v += __shfl_xor_sync(0xffffffffu, v, k);
        if (t == 0) red[0] = v;
    }
    __syncthreads();
    float mu = red[0] * (1.f / H);
    __syncthreads();
    float d = x - mu;
    float q = d * d;
    for (int k = 16; k; k >>= 1) q += __shfl_xor_sync(0xffffffffu, q, k);
    if ((t & 31) == 0) red[t >> 5] = q;
    __syncthreads();
    if (t < 32) {
        float v = (t < 8) ? red[t] : 0.f;
        for (int k = 4; k; k >>= 1) v += __shfl_xor_sync(0xffffffffu, v, k);
        if (t == 0) red[0] = v;
    }
    __syncthreads();
    float var = red[0] * (1.f / H);
    h[o] = d * rsqrtf(var + 1e-5f) * gg[t] + bb[t];
}

// ---------------------------------------------------------------------------
// Multi-head attention for one (b, head, q-chunk of 16 rows). Everything in smem.
__global__ __launch_bounds__(256) void attn_kernel(
    const float* __restrict__ q, const float* __restrict__ k,
    const float* __restrict__ v, float* __restrict__ ao)
{
    __shared__ float ks[128 * 65];   // k tile, pitch 65 (also reused for v, pitch 64)
    __shared__ float qs[16 * 64];
    __shared__ float ls[16 * 128];
    int qc = blockIdx.x, head = blockIdx.y, b = blockIdx.z;
    int t = threadIdx.x;

    const float* kb = k + b * R * H + head * DH;
    for (int idx = t; idx < 128 * 64; idx += 256) {
        int j = idx >> 6, d = idx & 63;
        ks[j * 65 + d] = kb[j * H + d];
    }
    const float* qb = q + (b * R + qc * 16) * H + head * DH;
    for (int idx = t; idx < 16 * 64; idx += 256) {
        int r = idx >> 6, d = idx & 63;
        qs[r * 64 + d] = qb[r * H + d];
    }
    __syncthreads();

    {   // logits
        int j = t & 127, g = t >> 7;
        float acc[8];
        #pragma unroll
        for (int r = 0; r < 8; r++) acc[r] = 0.f;
        for (int d = 0; d < 64; d++) {
            float kv = ks[j * 65 + d];
            #pragma unroll
            for (int r = 0; r < 8; r++) acc[r] += qs[(g * 8 + r) * 64 + d] * kv;
        }
        #pragma unroll
        for (int r = 0; r < 8; r++) ls[(g * 8 + r) * 128 + j] = acc[r] * 0.125f;
    }
    __syncthreads();

    {   // row softmax
        int qr = t >> 4, jc = t & 15;
        float e[8]; float mx = -3e38f;
        #pragma unroll
        for (int jj = 0; jj < 8; jj++) {
            e[jj] = ls[qr * 128 + jc * 8 + jj];
            mx = fmaxf(mx, e[jj]);
        }
        for (int o = 8; o; o >>= 1) mx = fmaxf(mx, __shfl_xor_sync(0xffffffffu, mx, o));
        float s = 0.f;
        #pragma unroll
        for (int jj = 0; jj < 8; jj++) { e[jj] = expf(e[jj] - mx); s += e[jj]; }
        for (int o = 8; o; o >>= 1) s += __shfl_xor_sync(0xffffffffu, s, o);
        float inv = 1.f / s;
        #pragma unroll
        for (int jj = 0; jj < 8; jj++) ls[qr * 128 + jc * 8 + jj] = e[jj] * inv;
    }
    float* vs = ks;
    const float* vb = v + b * R * H + head * DH;
    for (int idx = t; idx < 128 * 64; idx += 256) {
        int j = idx >> 6, d = idx & 63;
        vs[j * 64 + d] = vb[j * H + d];
    }
    __syncthreads();

    {   // out = P @ V
        int qr = t >> 4, d4 = (t & 15) * 4;
        float4 acc = {0, 0, 0, 0};
        for (int j = 0; j < 128; j++) {
            float p = ls[qr * 128 + j];
            float4 vv = *(const float4*)&vs[j * 64 + d4];
            acc.x += p * vv.x; acc.y += p * vv.y;
            acc.z += p * vv.z; acc.w += p * vv.w;
        }
        *(float4*)&ao[(b * R + qc * 16 + qr) * H + head * DH + d4] = acc;
    }
}

// ---------------------------------------------------------------------------
// abar = mean_r ao[b,r,:]; g = abar@Wo + bo; t = relu(g@roW1+rob1);
// logits = t@roW2+rob2; softmax -> out
__global__ void readout_kernel(const float* __restrict__ ao,
                               const float* __restrict__ Wo, const float* __restrict__ bo,
                               const float* __restrict__ roW1, const float* __restrict__ rob1,
                               const float* __restrict__ roW2, const float* __restrict__ rob2,
                               float* __restrict__ out) {
    __shared__ float s0[H], s1[H];
    __shared__ float red[8];
    int b = blockIdx.x, t = threadIdx.x;
    {
        float s = 0.f;
        const float* ap = ao + b * R * H + t;
        for (int r = 0; r < R; r++) s += ap[r * H];
        s0[t] = s * (1.f / R);
    }
    __syncthreads();
    float acc = bo[t];
    #pragma unroll 8
    for (int k = 0; k < H; k++) acc += s0[k] * Wo[k * H + t];
    s1[t] = acc;
    __syncthreads();
    acc = rob1[t];
    #pragma unroll 8
    for (int k = 0; k < H; k++) acc += s1[k] * roW1[k * H + t];
    __syncthreads();
    s0[t] = fmaxf(acc, 0.f);
    __syncthreads();
    float lg = -3e38f;
    if (t < R) {
        lg = rob2[t];
        #pragma unroll 8
        for (int k = 0; k < H; k++) lg += s0[k] * roW2[k * R + t];
    }
    float m = lg;
    for (int k = 16; k; k >>= 1) m = fmaxf(m, __shfl_xor_sync(0xffffffffu, m, k));
    if ((t & 31) == 0) red[t >> 5] = m;
    __syncthreads();
    if (t < 32) {
        float v = (t < 8) ? red[t] : -3e38f;
        for (int k = 4; k; k >>= 1) v = fmaxf(v, __shfl_xor_sync(0xffffffffu, v, k));
        if (t == 0) red[0] = v;
    }
    __syncthreads();
    float mx = red[0];
    __syncthreads();
    float e = (t < R) ? expf(lg - mx) : 0.f;
    float s = e;
    for (int k = 16; k; k >>= 1) s += __shfl_xor_sync(0xffffffffu, s, k);
    if ((t & 31) == 0) red[t >> 5] = s;
    __syncthreads();
    if (t < 32) {
        float v = (t < 8) ? red[t] : 0.f;
        for (int k = 4; k; k >>= 1) v += __shfl_xor_sync(0xffffffffu, v, k);
        if (t == 0) red[0] = v;
    }
    __syncthreads();
    float sum = red[0];
    if (t < R) out[b * R + t] = e / sum;
}

// ---------------------------------------------------------------------------
static inline GemmJob mkjob(const float* A, const float* W, float* C,
                            const float* bias = nullptr, const float* rowv = nullptr,
                            const float* colv = nullptr, const float* addend = nullptr,
                            int relu = 0) {
    GemmJob j;
    j.A = A; j.W = W; j.bias = bias; j.rowv = rowv; j.colv = colv;
    j.addend = addend; j.C = C; j.relu = relu;
    return j;
}

extern "C" void kernel_launch(void* const* d_in, const int* in_sizes, int n_in,
                              void* d_out, int out_size) {
    const float* x       = (const float*)d_in[0];
    const float* We      = (const float*)d_in[1];
    const float* be      = (const float*)d_in[2];
    const float* msg_W1  = (const float*)d_in[3];
    const float* msg_b1  = (const float*)d_in[4];
    const float* msg_W2  = (const float*)d_in[5];
    const float* msg_b2  = (const float*)d_in[6];
    const float* upd_W1  = (const float*)d_in[7];
    const float* upd_b1  = (const float*)d_in[8];
    const float* upd_W2  = (const float*)d_in[9];
    const float* upd_b2  = (const float*)d_in[10];
    const float* ln_g    = (const float*)d_in[11];
    const float* ln_b    = (const float*)d_in[12];
    const float* rule_adj= (const float*)d_in[13];
    const float* Wq      = (const float*)d_in[14];
    const float* bq      = (const float*)d_in[15];
    const float* Wk      = (const float*)d_in[16];
    const float* bk      = (const float*)d_in[17];
    const float* Wv      = (const float*)d_in[18];
    const float* bv      = (const float*)d_in[19];
    const float* Wo      = (const float*)d_in[20];
    const float* bo      = (const float*)d_in[21];
    const float* roW1    = (const float*)d_in[22];
    const float* rob1    = (const float*)d_in[23];
    const float* roW2    = (const float*)d_in[24];
    const float* rob2    = (const float*)d_in[25];
    float* out = (float*)d_out;

    float* base = nullptr;
    cudaGetSymbolAddress((void**)&base, g_buf);
    float* hb    = base + OFF_H;
    float* aact  = base + OFF_AACT;
    float* bbb   = base + OFF_BB;
    float* aggb  = base + OFF_AGG;
    float* hub   = base + OFF_HU;
    float* upreb = base + OFF_UPRE;
    float* ub    = base + OFF_U;
    float* qb    = base + OFF_Q;
    float* kb    = base + OFF_K;
    float* vb    = base + OFF_V;
    float* aob   = base + OFF_AO;
    float* Ab    = base + OFF_ADJ;
    float* rsb   = base + OFF_RS;
    float* w2ub  = base + OFF_W2U;
    float* c2b   = base + OFF_C2;

    const int M = B * R;  // 1024
    dim3 g1(4, M / 32, 1);      // single-job big GEMM
    dim3 g3(4, M / 32, 3);      // fused-3 big GEMM
    dim3 gw(4, H / 32, 3);      // fused-3 small GEMM (M=256)

    prep_A_kernel<<<R, R>>>(rule_adj, Ab, rsb);
    h0_kernel<<<B, H>>>(x, We, be, hb);
    c2_kernel<<<L, H>>>(msg_b2, upd_W1, c2b);

    // W2u[l] = msg_W2[l] @ upd_W1b[l]   (one fused launch over l)
    gemm_kernel<<<gw, 256>>>(
        mkjob(msg_W2 + 0 * HH, upd_W1 + 0 * 2 * HH + HH, w2ub + 0 * HH),
        mkjob(msg_W2 + 1 * HH, upd_W1 + 1 * 2 * HH + HH, w2ub + 1 * HH),
        mkjob(msg_W2 + 2 * HH, upd_W1 + 2 * 2 * HH + HH, w2ub + 2 * HH), H);

    for (int l = 0; l < L; l++) {
        const float* W1a = msg_W1 + l * 2 * HH;
        const float* W1b = W1a + HH;
        // fused: aact = h@W1a ; bb = h@W1b + b1 ; hu = h@Wu1a + b1u + rs*c2
        gemm_kernel<<<g3, 256>>>(
            mkjob(hb, W1a, aact),
            mkjob(hb, W1b, bbb, msg_b1 + l * H),
            mkjob(hb, upd_W1 + l * 2 * HH, hub, upd_b1 + l * H, rsb, c2b + l * H), M);
        agg_kernel<<<dim3(4, 4, B), 256>>>(aact, bbb, Ab, aggb);
        // upre = relu(agg@W2u + hu)
        {
            GemmJob j = mkjob(aggb, w2ub + l * HH, upreb, nullptr, nullptr, nullptr, hub, 1);
            gemm_kernel<<<g1, 256>>>(j, j, j, M);
        }
        // u = upre@Wu2 + b2u
        {
            GemmJob j = mkjob(upreb, upd_W2 + l * HH, ub, upd_b2 + l * H);
            gemm_kernel<<<g1, 256>>>(j, j, j, M);
        }
        ln_kernel<<<M, H>>>(hb, ub, ln_g + l * H, ln_b + l * H);
    }

    // fused q/k/v
    gemm_kernel<<<g3, 256>>>(
        mkjob(hb, Wq, qb, bq),
        mkjob(hb, Wk, kb, bk),
        mkjob(hb, Wv, vb, bv), M);
    attn_kernel<<<dim3(R / 16, NH, B), 256>>>(qb, kb, vb, aob);
    readout_kernel<<<B, H>>>(aob, Wo, bo, roW1, rob1, roW2, rob2, out);
    (void)in_sizes; (void)n_in; (void)out_size;
}